// round 5
// baseline (speedup 1.0000x reference)
#include <cuda_runtime.h>
#include <cuda_bf16.h>
#include <stdint.h>
#include <math.h>

#define N_NODES 50000
#define N_EDGES 800000
#define IN_F 128
#define OUT_F 128
#define BN_EPS 1e-5f
#define SCAN_BLKS 49    // ceil(50000/1024)

// ---------------- device scratch ----------------
__device__ float g_agg[N_NODES * IN_F];
__device__ int   g_deg[N_NODES];
__device__ int   g_start[N_NODES];
__device__ int   g_pos[N_NODES];
__device__ int   g_csr[N_EDGES];
__device__ int   g_blocksum[SCAN_BLKS];
__device__ __align__(16) __nv_bfloat16 g_Whi[OUT_F * 256];
__device__ __align__(16) __nv_bfloat16 g_Wlo[OUT_F * 256];
__device__ float g_bias[OUT_F];
__device__ float g_pre[N_NODES * OUT_F];
__device__ float g_sum[OUT_F];
__device__ float g_sumsq[OUT_F];
__device__ float g_scale[OUT_F];
__device__ float g_shift[OUT_F];
__device__ int   g_is64;

__device__ __forceinline__ uint32_t smem_u32(const void* p) {
    uint32_t a;
    asm("{ .reg .u64 t; cvta.to.shared.u64 t, %1; cvt.u32.u64 %0, t; }" : "=r"(a) : "l"(p));
    return a;
}
static __device__ __forceinline__ uint32_t pack2(__nv_bfloat16 a, __nv_bfloat16 b) {
    return (uint32_t)__bfloat16_as_ushort(a) | ((uint32_t)__bfloat16_as_ushort(b) << 16);
}

#define LDSM_X4(r, addr)                                                          \
    asm volatile("ldmatrix.sync.aligned.m8n8.x4.shared.b16 {%0,%1,%2,%3}, [%4];"  \
                 : "=r"((r)[0]), "=r"((r)[1]), "=r"((r)[2]), "=r"((r)[3])         \
                 : "r"(addr))
#define LDSM_X2(r, addr)                                                          \
    asm volatile("ldmatrix.sync.aligned.m8n8.x2.shared.b16 {%0,%1}, [%2];"        \
                 : "=r"((r)[0]), "=r"((r)[1]) : "r"(addr))
#define MMA_BF16(c, a, b)                                                         \
    asm volatile("mma.sync.aligned.m16n8k16.row.col.f32.bf16.bf16.f32 "           \
                 "{%0,%1,%2,%3}, {%4,%5,%6,%7}, {%8,%9}, {%0,%1,%2,%3};"          \
                 : "+f"((c)[0]), "+f"((c)[1]), "+f"((c)[2]), "+f"((c)[3])         \
                 : "r"((a)[0]), "r"((a)[1]), "r"((a)[2]), "r"((a)[3]),            \
                   "r"((b)[0]), "r"((b)[1]))

// ---------------- K0: zero counters + BN accumulators + dtype detect ----------------
__global__ void zero_kernel(const long long* __restrict__ ei) {
    int i = blockIdx.x * blockDim.x + threadIdx.x;
    int stride = gridDim.x * blockDim.x;
    for (int j = i; j < N_NODES; j += stride) g_deg[j] = 0;
    if (i < OUT_F) { g_sum[i] = 0.f; g_sumsq[i] = 0.f; }
    if (i == 0) {
        int ok = 1;
        for (int k = 0; k < 1024; ++k) {
            long long v = ei[k];
            if (v < 0 || v >= (long long)N_NODES) { ok = 0; break; }
        }
        g_is64 = ok;
    }
}

// ---------------- K1: fold circulant into weights; emit bf16 hi/lo ----------------
__global__ void precompute_kernel(const float* __restrict__ W_fuse,
                                  const float* __restrict__ b_fuse,
                                  const float* __restrict__ W_in,
                                  const float* __restrict__ b_in,
                                  const float* __restrict__ cw,
                                  const float* __restrict__ alpha_p) {
    __shared__ float k_sh[128];
    int t = blockIdx.x;
    int i = threadIdx.x;
    {
        float acc = cw[0];
        acc += cw[128] * ((i & 1) ? -1.f : 1.f);
        for (int f = 1; f < 64; ++f) {
            float wr = cw[2 * f], wi = cw[2 * f + 1];
            int m = (f * i) & 127;
            float theta = (float)m * (6.283185307179586f / 128.f);
            float s, c;
            sincosf(theta, &s, &c);
            acc += 2.f * (wr * c - wi * s);
        }
        k_sh[i] = acc * (1.f / 128.f);
    }
    __syncthreads();
    float alpha = *alpha_p;
    float w = 0.f;
    #pragma unroll 8
    for (int s = 0; s < 128; ++s)
        w += k_sh[(t - s) & 127] * W_in[s * IN_F + i];
    float wa = W_fuse[t * (2 * IN_F) + i] + alpha * w;
    float wb = W_fuse[t * (2 * IN_F) + IN_F + i];
    __nv_bfloat16 h;
    h = __float2bfloat16(wa);
    g_Whi[t * 256 + i] = h;
    g_Wlo[t * 256 + i] = __float2bfloat16(wa - __bfloat162float(h));
    h = __float2bfloat16(wb);
    g_Whi[t * 256 + 128 + i] = h;
    g_Wlo[t * 256 + 128 + i] = __float2bfloat16(wb - __bfloat162float(h));
    if (i == 0) {
        float b = 0.f;
        for (int s = 0; s < 128; ++s) b += k_sh[(t - s) & 127] * b_in[s];
        g_bias[t] = b_fuse[t] + alpha * b;
    }
}

// ---------------- K2a: histogram of dst (4 edges / thread, vector loads) --------
__global__ __launch_bounds__(256) void hist_kernel(const long long* __restrict__ ei) {
    int t = blockIdx.x * blockDim.x + threadIdx.x;
    if (t >= N_EDGES / 4) return;
    int d0, d1, d2, d3;
    if (g_is64) {
        longlong2 a = __ldg(reinterpret_cast<const longlong2*>(ei + N_EDGES) + t * 2);
        longlong2 b = __ldg(reinterpret_cast<const longlong2*>(ei + N_EDGES) + t * 2 + 1);
        d0 = (int)a.x; d1 = (int)a.y; d2 = (int)b.x; d3 = (int)b.y;
    } else {
        const int* p = (const int*)ei;
        int4 a = __ldg(reinterpret_cast<const int4*>(p + N_EDGES) + t);
        d0 = a.x; d1 = a.y; d2 = a.z; d3 = a.w;
    }
    atomicAdd(&g_deg[d0], 1);
    atomicAdd(&g_deg[d1], 1);
    atomicAdd(&g_deg[d2], 1);
    atomicAdd(&g_deg[d3], 1);
}

// ---------------- scan (3 small kernels) ----------------
__global__ __launch_bounds__(1024) void scanA_kernel() {
    __shared__ int wsum[32];
    int tid = threadIdx.x, lane = tid & 31, wid = tid >> 5;
    int i = blockIdx.x * 1024 + tid;
    int v = (i < N_NODES) ? g_deg[i] : 0;
    int s = v;
    #pragma unroll
    for (int d = 1; d < 32; d <<= 1) { int t = __shfl_up_sync(~0u, s, d); if (lane >= d) s += t; }
    if (lane == 31) wsum[wid] = s;
    __syncthreads();
    if (wid == 0) {
        int w = wsum[lane];
        #pragma unroll
        for (int d = 1; d < 32; d <<= 1) { int t = __shfl_up_sync(~0u, w, d); if (lane >= d) w += t; }
        wsum[lane] = w;
    }
    __syncthreads();
    int off = wid ? wsum[wid - 1] : 0;
    if (i < N_NODES) g_start[i] = s - v + off;
    if (tid == 1023) g_blocksum[blockIdx.x] = wsum[31];
}

__global__ void scanB_kernel() {
    if (threadIdx.x == 0) {
        int run = 0;
        for (int i = 0; i < SCAN_BLKS; ++i) { int t = g_blocksum[i]; g_blocksum[i] = run; run += t; }
    }
}

__global__ __launch_bounds__(1024) void scanC_kernel() {
    int i = blockIdx.x * 1024 + threadIdx.x;
    if (i >= N_NODES) return;
    int s = g_start[i] + g_blocksum[blockIdx.x];
    g_start[i] = s;
    g_pos[i] = s;
}

// ---------------- K2b: scatter src into CSR (4 edges / thread) ----------------
__global__ __launch_bounds__(256) void scatter_kernel(const long long* __restrict__ ei) {
    int t = blockIdx.x * blockDim.x + threadIdx.x;
    if (t >= N_EDGES / 4) return;
    int s0, s1, s2, s3, d0, d1, d2, d3;
    if (g_is64) {
        longlong2 a = __ldg(reinterpret_cast<const longlong2*>(ei) + t * 2);
        longlong2 b = __ldg(reinterpret_cast<const longlong2*>(ei) + t * 2 + 1);
        s0 = (int)a.x; s1 = (int)a.y; s2 = (int)b.x; s3 = (int)b.y;
        longlong2 c = __ldg(reinterpret_cast<const longlong2*>(ei + N_EDGES) + t * 2);
        longlong2 d = __ldg(reinterpret_cast<const longlong2*>(ei + N_EDGES) + t * 2 + 1);
        d0 = (int)c.x; d1 = (int)c.y; d2 = (int)d.x; d3 = (int)d.y;
    } else {
        const int* p = (const int*)ei;
        int4 a = __ldg(reinterpret_cast<const int4*>(p) + t);
        s0 = a.x; s1 = a.y; s2 = a.z; s3 = a.w;
        int4 b = __ldg(reinterpret_cast<const int4*>(p + N_EDGES) + t);
        d0 = b.x; d1 = b.y; d2 = b.z; d3 = b.w;
    }
    g_csr[atomicAdd(&g_pos[d0], 1)] = s0;
    g_csr[atomicAdd(&g_pos[d1], 1)] = s1;
    g_csr[atomicAdd(&g_pos[d2], 1)] = s2;
    g_csr[atomicAdd(&g_pos[d3], 1)] = s3;
}

// ---------------- gather: warp per node, mean of neighbor rows (unroll 8) -------
__global__ __launch_bounds__(256) void gather_kernel(const float* __restrict__ x) {
    int warp = (blockIdx.x * blockDim.x + threadIdx.x) >> 5;
    int lane = threadIdx.x & 31;
    if (warp >= N_NODES) return;
    int start = g_start[warp];
    int deg = g_deg[warp];
    int end = start + deg;
    float4 acc = make_float4(0.f, 0.f, 0.f, 0.f);
    int e = start;
    for (; e + 8 <= end; e += 8) {
        int s[8];
        #pragma unroll
        for (int j = 0; j < 8; ++j) s[j] = __ldg(&g_csr[e + j]);
        float4 v[8];
        #pragma unroll
        for (int j = 0; j < 8; ++j)
            v[j] = __ldg(reinterpret_cast<const float4*>(x + (size_t)s[j] * IN_F) + lane);
        #pragma unroll
        for (int j = 0; j < 8; ++j) {
            acc.x += v[j].x; acc.y += v[j].y; acc.z += v[j].z; acc.w += v[j].w;
        }
    }
    if (e + 4 <= end) {
        int s[4];
        #pragma unroll
        for (int j = 0; j < 4; ++j) s[j] = __ldg(&g_csr[e + j]);
        float4 v[4];
        #pragma unroll
        for (int j = 0; j < 4; ++j)
            v[j] = __ldg(reinterpret_cast<const float4*>(x + (size_t)s[j] * IN_F) + lane);
        #pragma unroll
        for (int j = 0; j < 4; ++j) {
            acc.x += v[j].x; acc.y += v[j].y; acc.z += v[j].z; acc.w += v[j].w;
        }
        e += 4;
    }
    for (; e < end; ++e) {
        int s = __ldg(&g_csr[e]);
        float4 v = __ldg(reinterpret_cast<const float4*>(x + (size_t)s * IN_F) + lane);
        acc.x += v.x; acc.y += v.y; acc.z += v.z; acc.w += v.w;
    }
    float rinv = 1.f / fmaxf((float)deg, 1.f);
    acc.x *= rinv; acc.y *= rinv; acc.z *= rinv; acc.w *= rinv;
    reinterpret_cast<float4*>(g_agg + (size_t)warp * IN_F)[lane] = acc;
}

// ---------------- K3: HMMA bf16 split-precision GEMM + fused BN partial stats ----
#define ROWSTR 72
#define TILE_B (128 * ROWSTR * 2)
#define GEMM_DSMEM (4 * TILE_B)
__global__ __launch_bounds__(256) void gemm_mma_kernel(const float* __restrict__ x) {
    extern __shared__ __align__(16) char dsm[];
    __nv_bfloat16* Ah = reinterpret_cast<__nv_bfloat16*>(dsm);
    __nv_bfloat16* Al = reinterpret_cast<__nv_bfloat16*>(dsm + TILE_B);
    __nv_bfloat16* Wh = reinterpret_cast<__nv_bfloat16*>(dsm + 2 * TILE_B);
    __nv_bfloat16* Wl = reinterpret_cast<__nv_bfloat16*>(dsm + 3 * TILE_B);

    __shared__ float s_bias[128];
    __shared__ float s_bsum[128];
    __shared__ float s_bsq[128];

    int tid = threadIdx.x;
    int wid = tid >> 5, lane = tid & 31;
    int row0 = blockIdx.x * 128;
    int wm = wid & 1;
    int wn = wid >> 1;

    if (tid < 128) {
        s_bias[tid] = g_bias[tid];
        s_bsum[tid] = 0.f;
        s_bsq[tid] = 0.f;
    }
    __syncthreads();

    float acc[4][4][4];
    #pragma unroll
    for (int a = 0; a < 4; ++a)
        #pragma unroll
        for (int b = 0; b < 4; ++b)
            #pragma unroll
            for (int c = 0; c < 4; ++c) acc[a][b][c] = 0.f;

    uint32_t Ah_b = smem_u32(Ah), Al_b = smem_u32(Al);
    uint32_t Wh_b = smem_u32(Wh), Wl_b = smem_u32(Wl);

    for (int kc = 0; kc < 4; ++kc) {
        const float* src = (kc < 2) ? x : g_agg;
        int koff = (kc & 1) * 64;
        if (kc) __syncthreads();
        #pragma unroll
        for (int l = 0; l < 8; ++l) {
            int idx = tid + l * 256;
            int r = idx >> 4, seg = idx & 15;
            int gr = row0 + r;
            if (gr >= N_NODES) gr = N_NODES - 1;
            float4 v = *reinterpret_cast<const float4*>(src + (size_t)gr * 128 + koff + seg * 4);
            __nv_bfloat16 h0 = __float2bfloat16(v.x), h1 = __float2bfloat16(v.y);
            __nv_bfloat16 h2 = __float2bfloat16(v.z), h3 = __float2bfloat16(v.w);
            __nv_bfloat16 l0 = __float2bfloat16(v.x - __bfloat162float(h0));
            __nv_bfloat16 l1 = __float2bfloat16(v.y - __bfloat162float(h1));
            __nv_bfloat16 l2 = __float2bfloat16(v.z - __bfloat162float(h2));
            __nv_bfloat16 l3 = __float2bfloat16(v.w - __bfloat162float(h3));
            int o = r * ROWSTR + seg * 4;
            *reinterpret_cast<uint2*>(Ah + o) = make_uint2(pack2(h0, h1), pack2(h2, h3));
            *reinterpret_cast<uint2*>(Al + o) = make_uint2(pack2(l0, l1), pack2(l2, l3));
        }
        #pragma unroll
        for (int l = 0; l < 4; ++l) {
            int idx = tid + l * 256;
            int n = idx >> 3, seg = idx & 7;
            uint4 vh = *reinterpret_cast<const uint4*>(g_Whi + n * 256 + kc * 64 + seg * 8);
            uint4 vl = *reinterpret_cast<const uint4*>(g_Wlo + n * 256 + kc * 64 + seg * 8);
            int o = n * ROWSTR + seg * 8;
            *reinterpret_cast<uint4*>(Wh + o) = vh;
            *reinterpret_cast<uint4*>(Wl + o) = vl;
        }
        __syncthreads();

        #pragma unroll
        for (int ks = 0; ks < 4; ++ks) {
            uint32_t ah[4][4], al[4][4], bh[4][2], bl[4][2];
            uint32_t aoff = (uint32_t)((wm * 64 + (lane & 15)) * ROWSTR + ks * 16 + (lane >> 4) * 8) * 2;
            #pragma unroll
            for (int mt = 0; mt < 4; ++mt) {
                LDSM_X4(ah[mt], Ah_b + aoff + mt * 16 * ROWSTR * 2);
                LDSM_X4(al[mt], Al_b + aoff + mt * 16 * ROWSTR * 2);
            }
            uint32_t boff = (uint32_t)((wn * 32 + (lane & 7)) * ROWSTR + ks * 16 + ((lane >> 3) & 1) * 8) * 2;
            #pragma unroll
            for (int nt = 0; nt < 4; ++nt) {
                LDSM_X2(bh[nt], Wh_b + boff + nt * 8 * ROWSTR * 2);
                LDSM_X2(bl[nt], Wl_b + boff + nt * 8 * ROWSTR * 2);
            }
            #pragma unroll
            for (int mt = 0; mt < 4; ++mt)
                #pragma unroll
                for (int nt = 0; nt < 4; ++nt) {
                    MMA_BF16(acc[mt][nt], ah[mt], bh[nt]);
                    MMA_BF16(acc[mt][nt], ah[mt], bl[nt]);
                    MMA_BF16(acc[mt][nt], al[mt], bh[nt]);
                }
        }
    }

    int lr = lane >> 2;
    int lc = (lane & 3) * 2;
    float scol[8], qcol[8];
    #pragma unroll
    for (int j = 0; j < 8; ++j) { scol[j] = 0.f; qcol[j] = 0.f; }
    #pragma unroll
    for (int mt = 0; mt < 4; ++mt) {
        #pragma unroll
        for (int h = 0; h < 2; ++h) {
            int r = row0 + wm * 64 + mt * 16 + lr + h * 8;
            bool valid = (r < N_NODES);
            #pragma unroll
            for (int nt = 0; nt < 4; ++nt) {
                int col = wn * 32 + nt * 8 + lc;
                float v0 = acc[mt][nt][h * 2 + 0] + s_bias[col];
                float v1 = acc[mt][nt][h * 2 + 1] + s_bias[col + 1];
                if (valid) {
                    *reinterpret_cast<float2*>(g_pre + (size_t)r * 128 + col) = make_float2(v0, v1);
                    scol[nt * 2 + 0] += v0; qcol[nt * 2 + 0] += v0 * v0;
                    scol[nt * 2 + 1] += v1; qcol[nt * 2 + 1] += v1 * v1;
                }
            }
        }
    }
    #pragma unroll
    for (int nt = 0; nt < 4; ++nt) {
        int col = wn * 32 + nt * 8 + lc;
        atomicAdd(&s_bsum[col], scol[nt * 2 + 0]);
        atomicAdd(&s_bsq[col], qcol[nt * 2 + 0]);
        atomicAdd(&s_bsum[col + 1], scol[nt * 2 + 1]);
        atomicAdd(&s_bsq[col + 1], qcol[nt * 2 + 1]);
    }
    __syncthreads();
    if (tid < 128) {
        atomicAdd(&g_sum[tid], s_bsum[tid]);
        atomicAdd(&g_sumsq[tid], s_bsq[tid]);
    }
}

// ---------------- K4: finalize BN statistics ----------------
__global__ void stats_kernel(const float* __restrict__ gamma,
                             const float* __restrict__ beta) {
    int c = threadIdx.x;
    float inv_n = 1.f / (float)N_NODES;
    float mean = g_sum[c] * inv_n;
    float var = fmaxf(g_sumsq[c] * inv_n - mean * mean, 0.f);
    float sc = gamma[c] / sqrtf(var + BN_EPS);
    g_scale[c] = sc;
    g_shift[c] = beta[c] - mean * sc;
}

// ---------------- K5: normalize + exact GELU ----------------
__global__ __launch_bounds__(256) void final_kernel(float* __restrict__ out) {
    int i = blockIdx.x * blockDim.x + threadIdx.x;
    if (i >= N_NODES * OUT_F / 4) return;
    int c = (i * 4) & 127;
    float4 v = reinterpret_cast<const float4*>(g_pre)[i];
    float sc0 = g_scale[c + 0], sh0 = g_shift[c + 0];
    float sc1 = g_scale[c + 1], sh1 = g_shift[c + 1];
    float sc2 = g_scale[c + 2], sh2 = g_shift[c + 2];
    float sc3 = g_scale[c + 3], sh3 = g_shift[c + 3];
    float r;
    r = fmaf(v.x, sc0, sh0); v.x = 0.5f * r * (1.f + erff(r * 0.70710678118654752f));
    r = fmaf(v.y, sc1, sh1); v.y = 0.5f * r * (1.f + erff(r * 0.70710678118654752f));
    r = fmaf(v.z, sc2, sh2); v.z = 0.5f * r * (1.f + erff(r * 0.70710678118654752f));
    r = fmaf(v.w, sc3, sh3); v.w = 0.5f * r * (1.f + erff(r * 0.70710678118654752f));
    reinterpret_cast<float4*>(out)[i] = v;
}

// ---------------- launcher ----------------
extern "C" void kernel_launch(void* const* d_in, const int* in_sizes, int n_in,
                              void* d_out, int out_size) {
    const float* x      = (const float*)d_in[0];
    const long long* ei = (const long long*)d_in[1];
    const float* W_fuse = (const float*)d_in[2];
    const float* b_fuse = (const float*)d_in[3];
    const float* W_in   = (const float*)d_in[4];
    const float* b_in   = (const float*)d_in[5];
    const float* cw     = (const float*)d_in[6];
    const float* alpha  = (const float*)d_in[7];
    const float* gamma  = (const float*)d_in[8];
    const float* beta   = (const float*)d_in[9];
    float* out          = (float*)d_out;

    cudaFuncSetAttribute(gemm_mma_kernel, cudaFuncAttributeMaxDynamicSharedMemorySize, GEMM_DSMEM);

    zero_kernel<<<256, 256>>>(ei);
    precompute_kernel<<<128, 128>>>(W_fuse, b_fuse, W_in, b_in, cw, alpha);
    hist_kernel<<<(N_EDGES / 4 + 255) / 256, 256>>>(ei);
    scanA_kernel<<<SCAN_BLKS, 1024>>>();
    scanB_kernel<<<1, 32>>>();
    scanC_kernel<<<SCAN_BLKS, 1024>>>();
    scatter_kernel<<<(N_EDGES / 4 + 255) / 256, 256>>>(ei);
    gather_kernel<<<(N_NODES * 32 + 255) / 256, 256>>>(x);
    gemm_mma_kernel<<<(N_NODES + 127) / 128, 256, GEMM_DSMEM>>>(x);
    stats_kernel<<<1, 128>>>(gamma, beta);
    final_kernel<<<(N_NODES * OUT_F / 4 + 255) / 256, 256>>>(out);
}